// round 11
// baseline (speedup 1.0000x reference)
#include <cuda_runtime.h>
#include <cstdint>

// NNUE HalfKP forward — tensor-core (IMMA) formulation.
//   hx_gemm: grid (64 kings x 4 K-chunks of 160 feats). Per block: stage W chunk
//            int32 -> lo(u8)/hi(s8) byte planes in SMEM; bucket pairs by king;
//            build 5 occupancy mask words per pair; mma.sync m16n8k32 with
//            A-fragments expanded from mask bits (0/1 bytes). Out: int32 partials
//            g_part[chunk][pair][256] = pp·lo + 256*(pp·hi)  (exact int32).
//            Block (0,0) zeroes scalars and pre-packs FC weights.
//   hx_phaseB: warp per sample: sum 4 chunks x 2 sides + 2 king bias rows +
//            input_bias in int32, (short) cast == ref astype(int16), clip,
//            FC1/FC2 from packed-transposed global weights, output dot,
//            atomicAdd; last block writes floor_div(total+out_b,16) as float.
//
// Inputs (ALL integers widened to int32 by the harness):
//  0 piece_positions (B,640)  1 king_positions (B,2)  2 input_weights (64,641,256)
//  3 input_bias (256)  4 w1 (32,512)  5 b1 (32)  6 w2 (32,32)  7 b2 (32)
//  8 out_w (32)  9 out_b (1)        out: float32 (1)

#define KC      4      // K chunks
#define KF      160    // features per chunk
#define KSTEPS  5      // 160 / 32
#define BCAP    80     // per-king bucket capacity (mean 32, +8.6 sigma)
#define MAXP    2048
#define BSTRIDE 176    // byte stride per dim row in staged planes (conflict-free)

__device__ int      g_part[KC][MAXP][256];   // int32 partial sums (8 MB)
__device__ unsigned g_w1t[128 * 32];
__device__ int      g_w2t[32 * 32];
__device__ int      g_total;
__device__ int      g_done;

__device__ __forceinline__ unsigned expand4(unsigned x) {
    // 4 bits -> 4 bytes of 0/1 (byte i = bit i)
    return (x * 0x00204081u) & 0x01010101u;
}

__device__ __forceinline__ void mma_uu(int c[4], const unsigned a[4],
                                       unsigned b0, unsigned b1) {
    asm volatile(
        "mma.sync.aligned.m16n8k32.row.col.s32.u8.u8.s32 "
        "{%0,%1,%2,%3}, {%4,%5,%6,%7}, {%8,%9}, {%0,%1,%2,%3};"
        : "+r"(c[0]), "+r"(c[1]), "+r"(c[2]), "+r"(c[3])
        : "r"(a[0]), "r"(a[1]), "r"(a[2]), "r"(a[3]), "r"(b0), "r"(b1));
}
__device__ __forceinline__ void mma_us(int c[4], const unsigned a[4],
                                       unsigned b0, unsigned b1) {
    asm volatile(
        "mma.sync.aligned.m16n8k32.row.col.s32.u8.s8.s32 "
        "{%0,%1,%2,%3}, {%4,%5,%6,%7}, {%8,%9}, {%0,%1,%2,%3};"
        : "+r"(c[0]), "+r"(c[1]), "+r"(c[2]), "+r"(c[3])
        : "r"(a[0]), "r"(a[1]), "r"(a[2]), "r"(a[3]), "r"(b0), "r"(b1));
}

// ---------------- GEMM phase ----------------
__global__ void __launch_bounds__(256, 2) hx_gemm(
    const int* __restrict__ W32,
    const int* __restrict__ pp,
    const int* __restrict__ kings,
    const int* __restrict__ w1,
    const int* __restrict__ w2,
    int B)
{
    extern __shared__ unsigned char smdyn[];
    unsigned char* s_lo = smdyn;                       // [256][BSTRIDE] u8
    unsigned char* s_hi = smdyn + 256 * BSTRIDE;       // [256][BSTRIDE] s8
    __shared__ int      s_bucket[BCAP];
    __shared__ unsigned s_masks[BCAP][KSTEPS];
    __shared__ int      s_cnt;

    const int kng = blockIdx.x;
    const int ch  = blockIdx.y;
    const int K0  = ch * KF;
    const int lane = threadIdx.x & 31;
    const int wid  = threadIdx.x >> 5;

    if (kng == 0 && ch == 0) {
        if (threadIdx.x == 0) { g_total = 0; g_done = 0; }
        for (int t = threadIdx.x; t < 32 * 128; t += 256) {
            const int o = t >> 7, j = t & 127;
            const int* p = w1 + t * 4;
            g_w1t[j * 32 + o] =
                (unsigned)(p[0] & 0xff) | ((unsigned)(p[1] & 0xff) << 8) |
                ((unsigned)(p[2] & 0xff) << 16) | ((unsigned)p[3] << 24);
        }
        for (int t = threadIdx.x; t < 32 * 32; t += 256)
            g_w2t[(t & 31) * 32 + (t >> 5)] = w2[t];
    }

    if (threadIdx.x == 0) s_cnt = 0;
    for (int i = threadIdx.x; i < BCAP * KSTEPS; i += 256)
        ((unsigned*)s_masks)[i] = 0;

    // kings[] scan into registers (in flight under staging)
    const int P = 2 * B;
    int kv[8];
    int nk = 0;
    #pragma unroll
    for (int j = 0; j < 8; j++) {
        const int i = threadIdx.x + j * 256;
        if (i < P) { kv[nk] = kings[i]; nk++; }
    }

    // stage W chunk: int32 -> lo/hi byte planes, k-contiguous per dim row
    {
        const int d = wid * 32 + lane;                 // dim 0..255
        const int* wb = W32 + ((size_t)kng * 641 + K0) * 256 + d;
        unsigned char* pl = s_lo + d * BSTRIDE;
        unsigned char* ph = s_hi + d * BSTRIDE;
        #pragma unroll 4
        for (int f = 0; f < KF; f += 2) {
            const int v0 = wb[(size_t)f * 256];
            const int v1 = wb[(size_t)(f + 1) * 256];
            *(unsigned short*)(pl + f) =
                (unsigned short)((v0 & 0xFF) | ((v1 & 0xFF) << 8));
            *(unsigned short*)(ph + f) =
                (unsigned short)(((v0 >> 8) & 0xFF) | (((v1 >> 8) & 0xFF) << 8));
        }
    }
    __syncthreads();

    // bucket pairs of this king
    for (int j = 0; j < nk; j++)
        if (kv[j] == kng) {
            const int slot = atomicAdd(&s_cnt, 1);
            if (slot < BCAP) s_bucket[slot] = threadIdx.x + j * 256;
        }
    __syncthreads();

    const int cnt = min(s_cnt, BCAP);
    // masks: 5 words of 32 features per pair (this chunk only)
    for (int pi = wid; pi < cnt; pi += 8) {
        const int sidx = s_bucket[pi] >> 1;
        const int* base = pp + (size_t)sidx * 640 + K0;
        #pragma unroll
        for (int j = 0; j < KSTEPS; j++) {
            const unsigned m = __ballot_sync(0xffffffffu, base[j * 32 + lane] != 0);
            if (lane == 0) s_masks[pi][j] = m;
        }
    }
    __syncthreads();

    if (cnt == 0) return;
    const int g  = lane >> 2;
    const int tg = lane & 3;
    const int Mt = (cnt + 15) >> 4;
    const int ntg = wid & 3;

    for (int mt = (wid >> 2); mt < Mt; mt += 2) {
        const int rA = mt * 16 + g;
        const int rB = rA + 8;
        // A fragments for all 5 K-steps from mask bits
        unsigned a[KSTEPS][4];
        #pragma unroll
        for (int s5 = 0; s5 < KSTEPS; s5++) {
            const unsigned wA = s_masks[rA][s5];
            const unsigned wB = s_masks[rB][s5];
            a[s5][0] = expand4((wA >> (tg * 4)) & 0xFu);
            a[s5][1] = expand4((wB >> (tg * 4)) & 0xFu);
            a[s5][2] = expand4((wA >> (16 + tg * 4)) & 0xFu);
            a[s5][3] = expand4((wB >> (16 + tg * 4)) & 0xFu);
        }
        const int pidA = (rA < cnt) ? s_bucket[rA] : -1;
        const int pidB = (rB < cnt) ? s_bucket[rB] : -1;

        #pragma unroll
        for (int i = 0; i < 8; i++) {
            const int ntl = ntg * 8 + i;                  // n-tile of 8 dims
            const unsigned char* pl = s_lo + (size_t)(ntl * 8 + g) * BSTRIDE;
            const unsigned char* ph = s_hi + (size_t)(ntl * 8 + g) * BSTRIDE;
            int clo[4] = {0, 0, 0, 0};
            int chi[4] = {0, 0, 0, 0};
            #pragma unroll
            for (int s5 = 0; s5 < KSTEPS; s5++) {
                const unsigned bl0 = *(const unsigned*)(pl + s5 * 32 + tg * 4);
                const unsigned bl1 = *(const unsigned*)(pl + s5 * 32 + 16 + tg * 4);
                const unsigned bh0 = *(const unsigned*)(ph + s5 * 32 + tg * 4);
                const unsigned bh1 = *(const unsigned*)(ph + s5 * 32 + 16 + tg * 4);
                mma_uu(clo, a[s5], bl0, bl1);
                mma_us(chi, a[s5], bh0, bh1);
            }
            const int d0 = ntl * 8 + tg * 2;
            if (pidA >= 0)
                *(int2*)&g_part[ch][pidA][d0] =
                    make_int2(clo[0] + (chi[0] << 8), clo[1] + (chi[1] << 8));
            if (pidB >= 0)
                *(int2*)&g_part[ch][pidB][d0] =
                    make_int2(clo[2] + (chi[2] << 8), clo[3] + (chi[3] << 8));
        }
    }
}

// ---------------- phase B: combine + FC + finalize ----------------
__global__ void __launch_bounds__(256, 1) hx_phaseB(
    const int* __restrict__ W32,
    const int* __restrict__ kings,
    const int* __restrict__ bias,
    const int* __restrict__ b1,
    const int* __restrict__ b2,
    const int* __restrict__ ow,
    const int* __restrict__ ob,
    float* __restrict__ out,
    int B, int nblocks)
{
    __shared__ unsigned s_x[8][64];
    __shared__ int      s_x1[8][32];
    __shared__ int      s_wsum[8];

    const int warp = threadIdx.x >> 5;
    const int lane = threadIdx.x & 31;
    const int s = blockIdx.x * 8 + warp;
    int contrib = 0;

    if (s < B) {
        const int dbase = lane * 8;
        // load 4 chunks x 2 sides (16 int4) + 2 king bias rows + input bias
        int4 pr[16];
        #pragma unroll
        for (int c = 0; c < KC; c++)
            #pragma unroll
            for (int side = 0; side < 2; side++) {
                const int* p = &g_part[c][2 * s + side][dbase];
                pr[(c * 2 + side) * 2 + 0] = *(const int4*)p;
                pr[(c * 2 + side) * 2 + 1] = *(const int4*)(p + 4);
            }
        const int k0 = kings[2 * s + 0];
        const int k1 = kings[2 * s + 1];
        const int* kb0p = W32 + ((size_t)k0 * 641 + 640) * 256 + dbase;
        const int* kb1p = W32 + ((size_t)k1 * 641 + 640) * 256 + dbase;
        const int4 kb0a = *(const int4*)kb0p, kb0b = *(const int4*)(kb0p + 4);
        const int4 kb1a = *(const int4*)kb1p, kb1b = *(const int4*)(kb1p + 4);
        const int4 bia  = ((const int4*)bias)[lane * 2 + 0];
        const int4 bib  = ((const int4*)bias)[lane * 2 + 1];

        int t0 = 0, t1 = 0, t2 = 0, t3 = 0, t4 = 0, t5 = 0, t6 = 0, t7 = 0;
        #pragma unroll
        for (int i = 0; i < 8; i++) {
            t0 += pr[2 * i].x;     t1 += pr[2 * i].y;
            t2 += pr[2 * i].z;     t3 += pr[2 * i].w;
            t4 += pr[2 * i + 1].x; t5 += pr[2 * i + 1].y;
            t6 += pr[2 * i + 1].z; t7 += pr[2 * i + 1].w;
        }
        t0 += kb0a.x + kb1a.x + bia.x;  t1 += kb0a.y + kb1a.y + bia.y;
        t2 += kb0a.z + kb1a.z + bia.z;  t3 += kb0a.w + kb1a.w + bia.w;
        t4 += kb0b.x + kb1b.x + bib.x;  t5 += kb0b.y + kb1b.y + bib.y;
        t6 += kb0b.z + kb1b.z + bib.z;  t7 += kb0b.w + kb1b.w + bib.w;

        // int16 wraparound cast, clip to [0,127], pack 8 int8 into 2 words
        int tt[8] = {t0, t1, t2, t3, t4, t5, t6, t7};
        int c8[8];
        #pragma unroll
        for (int j = 0; j < 8; j++)
            c8[j] = min(max((int)(short)tt[j], 0), 127);
        s_x[warp][lane * 2 + 0] = (unsigned)c8[0] | ((unsigned)c8[1] << 8) |
                                  ((unsigned)c8[2] << 16) | ((unsigned)c8[3] << 24);
        s_x[warp][lane * 2 + 1] = (unsigned)c8[4] | ((unsigned)c8[5] << 8) |
                                  ((unsigned)c8[6] << 16) | ((unsigned)c8[7] << 24);
        __syncwarp();

        // FC1: lane = output unit; x512 = [x, x]; 4 independent dp4a chains
        int v1a = b1[lane], v1b = 0, v1c = 0, v1d = 0;
        #pragma unroll 8
        for (int j = 0; j < 64; j += 2) {
            const int x0 = (int)s_x[warp][j];
            const int x1 = (int)s_x[warp][j + 1];
            v1a = __dp4a(x0, (int)__ldg(&g_w1t[j * 32 + lane]),        v1a);
            v1b = __dp4a(x0, (int)__ldg(&g_w1t[(64 + j) * 32 + lane]), v1b);
            v1c = __dp4a(x1, (int)__ldg(&g_w1t[(j + 1) * 32 + lane]),  v1c);
            v1d = __dp4a(x1, (int)__ldg(&g_w1t[(65 + j) * 32 + lane]), v1d);
        }
        int v1s = (v1a + v1b) + (v1c + v1d);
        v1s >>= 6;
        v1s = min(max(v1s, 0), 127);
        s_x1[warp][lane] = v1s;
        __syncwarp();

        // FC2
        int v2a = b2[lane], v2b = 0;
        #pragma unroll 8
        for (int o = 0; o < 32; o += 2) {
            v2a += s_x1[warp][o]     * __ldg(&g_w2t[o * 32 + lane]);
            v2b += s_x1[warp][o + 1] * __ldg(&g_w2t[(o + 1) * 32 + lane]);
        }
        int v2 = v2a + v2b;
        v2 >>= 6;
        v2 = min(max(v2, 0), 127);

        contrib = v2 * ow[lane];
        #pragma unroll
        for (int sh = 16; sh; sh >>= 1)
            contrib += __shfl_xor_sync(0xffffffffu, contrib, sh);
    }

    if (lane == 0) s_wsum[warp] = contrib;
    __syncthreads();
    if (threadIdx.x == 0) {
        int t = 0;
        #pragma unroll
        for (int w = 0; w < 8; w++) t += s_wsum[w];
        atomicAdd(&g_total, t);
        __threadfence();
        if (atomicAdd(&g_done, 1) == nblocks - 1) {
            const int tot = atomicAdd(&g_total, 0);
            out[0] = (float)((tot + ob[0]) >> 4);
        }
    }
}

extern "C" void kernel_launch(void* const* d_in, const int* in_sizes, int n_in,
                              void* d_out, int out_size) {
    const int B = in_sizes[0] / 640;
    const int sblocks = (B + 7) / 8;
    const int dynsmem = 2 * 256 * BSTRIDE;

    static bool attr_set = false;
    if (!attr_set) {
        cudaFuncSetAttribute(hx_gemm,
            cudaFuncAttributeMaxDynamicSharedMemorySize, dynsmem);
        attr_set = true;
    }

    hx_gemm<<<dim3(64, KC), 256, dynsmem>>>(
        (const int*)d_in[2], (const int*)d_in[0], (const int*)d_in[1],
        (const int*)d_in[4], (const int*)d_in[6], B);
    hx_phaseB<<<sblocks, 256>>>(
        (const int*)d_in[2],
        (const int*)d_in[1],
        (const int*)d_in[3],
        (const int*)d_in[5],
        (const int*)d_in[7],
        (const int*)d_in[8],
        (const int*)d_in[9],
        (float*)d_out,
        B, sblocks);
}

// round 12
// speedup vs baseline: 1.2288x; 1.2288x over previous
#include <cuda_runtime.h>
#include <cstdint>

// NNUE HalfKP forward — king-grouped, 2-kernel formulation.
//   phaseA: grid (64 kings x 10 row-slices of 64). 32 KB tile, 4 blocks/SM
//           (~1.08 waves), 8 warps x 4 pairs => every warp works. Dense 64-row
//           loop: one LDS.128 per row feeds 4 pairs via predicated vadd2
//           (packed int16). Block (0,0) zeroes scalars + pre-packs FC weights.
//   phaseB: warp per sample; 20 partials in one register batch (MLP~20),
//           + 2 king bias rows + input_bias (mod 2^16 == ref astype(int16)),
//           clip, FC1/FC2 from L1-resident packed-transposed global weights,
//           output dot, atomicAdd; last block writes floor_div(total+out_b,16).
//
// Inputs (ALL integers widened to int32 by the harness):
//  0 piece_positions (B,640)  1 king_positions (B,2)  2 input_weights (64,641,256)
//  3 input_bias (256)  4 w1 (32,512)  5 b1 (32)  6 w2 (32,32)  7 b2 (32)
//  8 out_w (32)  9 out_b (1)        out: float32 (1)

#define NQ    10                 // row slices
#define QR    64                 // rows per slice
#define MAXP  2048               // max (sample,side) pairs (B <= 1024)
#define BCAP  128                // per-king bucket capacity (mean 32, sd 5.6)

__device__ uint4    g_part[NQ][MAXP * 32];   // packed-int16 partial sums (10 MB)
__device__ unsigned g_w1t[128 * 32];         // dp4a-packed w1, j-major [j*32+out]
__device__ int      g_w2t[32 * 32];          // w2 transposed [in*32+out]
__device__ int      g_total;
__device__ int      g_done;

// ---------------- phase A ----------------
__global__ void __launch_bounds__(256, 4) hx_phaseA(
    const int* __restrict__ W32,
    const int* __restrict__ pp,
    const int* __restrict__ kings,
    const int* __restrict__ w1,
    const int* __restrict__ w2,
    int B)
{
    __shared__ short s_tile[QR * 256];    // 32 KB
    __shared__ int   s_bucket[BCAP];
    __shared__ int   s_cnt;

    const int k = blockIdx.x;
    const int q = blockIdx.y;

    if (k == 0 && q == 0) {
        if (threadIdx.x == 0) { g_total = 0; g_done = 0; }
        for (int t = threadIdx.x; t < 32 * 128; t += 256) {
            const int o = t >> 7, j = t & 127;
            const int* p = w1 + t * 4;
            g_w1t[j * 32 + o] =
                (unsigned)(p[0] & 0xff) | ((unsigned)(p[1] & 0xff) << 8) |
                ((unsigned)(p[2] & 0xff) << 16) | ((unsigned)p[3] << 24);
        }
        for (int t = threadIdx.x; t < 32 * 32; t += 256)
            g_w2t[(t & 31) * 32 + (t >> 5)] = w2[t];
    }
    if (threadIdx.x == 0) s_cnt = 0;

    // 1) kings[] scan loads into registers (in flight during tile staging)
    const int P = 2 * B;
    int kv[8];
    int nk = 0;
    #pragma unroll
    for (int j = 0; j < 8; j++) {
        const int i = threadIdx.x + j * 256;
        if (i < P) { kv[nk] = kings[i]; nk++; }
    }

    // 2) stage + narrow tile: rows [q*64, q*64+64) int32 -> int16 SMEM
    {
        const int4* src = (const int4*)(W32 + ((size_t)k * 641 + (size_t)q * QR) * 256);
        short4* dst = (short4*)s_tile;
        #pragma unroll 4
        for (int i = threadIdx.x; i < QR * 256 / 4; i += 256) {
            const int4 v = src[i];
            dst[i] = make_short4((short)v.x, (short)v.y, (short)v.z, (short)v.w);
        }
    }

    // 3) bucket the scanned pairs
    __syncthreads();   // s_cnt visible
    for (int j = 0; j < nk; j++)
        if (kv[j] == k) {
            const int slot = atomicAdd(&s_cnt, 1);
            if (slot < BCAP) s_bucket[slot] = threadIdx.x + j * 256;
        }
    __syncthreads();

    const int cnt = min(s_cnt, BCAP);
    const int warp = threadIdx.x >> 5;
    const int lane = threadIdx.x & 31;
    const char* tb = (const char*)s_tile + lane * 16;   // lane covers 8 dims

    // 8 warps x 4 pairs each; strided if cnt > 32
    for (int gb = warp * 4; gb < cnt; gb += 32) {
        const int npair = min(4, cnt - gb);

        unsigned m0[4], m1[4];
        int pid[4];
        #pragma unroll
        for (int j = 0; j < 4; j++) {
            const bool valid = (j < npair);
            const int  p = s_bucket[valid ? (gb + j) : gb];
            pid[j] = p;
            const int* ppq = pp + (size_t)(p >> 1) * 640 + q * QR;
            const unsigned b0 = __ballot_sync(0xffffffffu, ppq[lane]      != 0);
            const unsigned b1 = __ballot_sync(0xffffffffu, ppq[32 + lane] != 0);
            m0[j] = valid ? b0 : 0u;
            m1[j] = valid ? b1 : 0u;
        }

        unsigned acc[4][4];
        #pragma unroll
        for (int j = 0; j < 4; j++)
            acc[j][0] = acc[j][1] = acc[j][2] = acc[j][3] = 0u;

        #pragma unroll
        for (int r = 0; r < 32; r++) {
            const uint4 row = *(const uint4*)(tb + (r << 9));
            #pragma unroll
            for (int j = 0; j < 4; j++) {
                if (m0[j] & (1u << r)) {
                    acc[j][0] = __vadd2(acc[j][0], row.x);
                    acc[j][1] = __vadd2(acc[j][1], row.y);
                    acc[j][2] = __vadd2(acc[j][2], row.z);
                    acc[j][3] = __vadd2(acc[j][3], row.w);
                }
            }
        }
        const char* tb1 = tb + (32 << 9);
        #pragma unroll
        for (int r = 0; r < 32; r++) {
            const uint4 row = *(const uint4*)(tb1 + (r << 9));
            #pragma unroll
            for (int j = 0; j < 4; j++) {
                if (m1[j] & (1u << r)) {
                    acc[j][0] = __vadd2(acc[j][0], row.x);
                    acc[j][1] = __vadd2(acc[j][1], row.y);
                    acc[j][2] = __vadd2(acc[j][2], row.z);
                    acc[j][3] = __vadd2(acc[j][3], row.w);
                }
            }
        }

        #pragma unroll
        for (int j = 0; j < 4; j++)
            if (j < npair)
                g_part[q][pid[j] * 32 + lane] =
                    make_uint4(acc[j][0], acc[j][1], acc[j][2], acc[j][3]);
    }
}

// ---------------- phase B: combine + FC + finalize ----------------
__global__ void __launch_bounds__(256, 1) hx_phaseB(
    const int* __restrict__ W32,
    const int* __restrict__ kings,
    const int* __restrict__ bias,
    const int* __restrict__ b1,
    const int* __restrict__ b2,
    const int* __restrict__ ow,
    const int* __restrict__ ob,
    float* __restrict__ out,
    int B, int nblocks)
{
    __shared__ unsigned s_x[8][64];
    __shared__ int      s_x1[8][32];
    __shared__ int      s_wsum[8];

    const int warp = threadIdx.x >> 5;
    const int lane = threadIdx.x & 31;
    const int s = blockIdx.x * 8 + warp;
    int contrib = 0;

    if (s < B) {
        // ---- load ALL partials + bias rows first: ~26 loads in flight ----
        uint4 r[20];
        #pragma unroll
        for (int q = 0; q < NQ; q++) {
            r[2 * q + 0] = g_part[q][(2 * s + 0) * 32 + lane];
            r[2 * q + 1] = g_part[q][(2 * s + 1) * 32 + lane];
        }
        const int k0 = kings[2 * s + 0];
        const int k1 = kings[2 * s + 1];
        const int4* br0 = (const int4*)(W32 + ((size_t)k0 * 641 + 640) * 256 + lane * 8);
        const int4* br1 = (const int4*)(W32 + ((size_t)k1 * 641 + 640) * 256 + lane * 8);
        const int4 u0 = br0[0], v0 = br0[1];
        const int4 u1 = br1[0], v1 = br1[1];
        const int4 bA = ((const int4*)bias)[lane * 2 + 0];
        const int4 bB = ((const int4*)bias)[lane * 2 + 1];

        // ---- reduce (packed int16, mod 2^16 exact) ----
        unsigned a0 = 0, a1 = 0, a2 = 0, a3 = 0;
        #pragma unroll
        for (int i = 0; i < 20; i++) {
            a0 = __vadd2(a0, r[i].x); a1 = __vadd2(a1, r[i].y);
            a2 = __vadd2(a2, r[i].z); a3 = __vadd2(a3, r[i].w);
        }
        a0 = __vadd2(a0, (unsigned)(u0.x & 0xffff) | ((unsigned)u0.y << 16));
        a1 = __vadd2(a1, (unsigned)(u0.z & 0xffff) | ((unsigned)u0.w << 16));
        a2 = __vadd2(a2, (unsigned)(v0.x & 0xffff) | ((unsigned)v0.y << 16));
        a3 = __vadd2(a3, (unsigned)(v0.z & 0xffff) | ((unsigned)v0.w << 16));
        a0 = __vadd2(a0, (unsigned)(u1.x & 0xffff) | ((unsigned)u1.y << 16));
        a1 = __vadd2(a1, (unsigned)(u1.z & 0xffff) | ((unsigned)u1.w << 16));
        a2 = __vadd2(a2, (unsigned)(v1.x & 0xffff) | ((unsigned)v1.y << 16));
        a3 = __vadd2(a3, (unsigned)(v1.z & 0xffff) | ((unsigned)v1.w << 16));
        a0 = __vadd2(a0, (unsigned)(bA.x & 0xffff) | ((unsigned)bA.y << 16));
        a1 = __vadd2(a1, (unsigned)(bA.z & 0xffff) | ((unsigned)bA.w << 16));
        a2 = __vadd2(a2, (unsigned)(bB.x & 0xffff) | ((unsigned)bB.y << 16));
        a3 = __vadd2(a3, (unsigned)(bB.z & 0xffff) | ((unsigned)bB.w << 16));

        // clip int16 -> [0,127], pack 8 int8 into 2 words
        unsigned accs[4] = {a0, a1, a2, a3};
        int c8[8];
        #pragma unroll
        for (int kk = 0; kk < 4; kk++) {
            int lo = (int)(short)(accs[kk] & 0xffffu);
            int hi = (int)(short)(accs[kk] >> 16);
            c8[2 * kk + 0] = min(max(lo, 0), 127);
            c8[2 * kk + 1] = min(max(hi, 0), 127);
        }
        s_x[warp][lane * 2 + 0] = (unsigned)c8[0] | ((unsigned)c8[1] << 8) |
                                  ((unsigned)c8[2] << 16) | ((unsigned)c8[3] << 24);
        s_x[warp][lane * 2 + 1] = (unsigned)c8[4] | ((unsigned)c8[5] << 8) |
                                  ((unsigned)c8[6] << 16) | ((unsigned)c8[7] << 24);
        __syncwarp();

        // FC1: lane = output unit; x512 = [x, x]; 4 independent dp4a chains
        int v1a = b1[lane], v1b = 0, v1c = 0, v1d = 0;
        #pragma unroll 8
        for (int j = 0; j < 64; j += 2) {
            const int x0 = (int)s_x[warp][j];
            const int x1 = (int)s_x[warp][j + 1];
            v1a = __dp4a(x0, (int)__ldg(&g_w1t[j * 32 + lane]),        v1a);
            v1b = __dp4a(x0, (int)__ldg(&g_w1t[(64 + j) * 32 + lane]), v1b);
            v1c = __dp4a(x1, (int)__ldg(&g_w1t[(j + 1) * 32 + lane]),  v1c);
            v1d = __dp4a(x1, (int)__ldg(&g_w1t[(65 + j) * 32 + lane]), v1d);
        }
        int v1s = (v1a + v1b) + (v1c + v1d);
        v1s >>= 6;
        v1s = min(max(v1s, 0), 127);
        s_x1[warp][lane] = v1s;
        __syncwarp();

        // FC2 from transposed global (coalesced, L1-resident), 2 chains
        int v2a = b2[lane], v2b = 0;
        #pragma unroll 8
        for (int o = 0; o < 32; o += 2) {
            v2a += s_x1[warp][o]     * __ldg(&g_w2t[o * 32 + lane]);
            v2b += s_x1[warp][o + 1] * __ldg(&g_w2t[(o + 1) * 32 + lane]);
        }
        int v2 = v2a + v2b;
        v2 >>= 6;
        v2 = min(max(v2, 0), 127);

        contrib = v2 * ow[lane];
        #pragma unroll
        for (int sh = 16; sh; sh >>= 1)
            contrib += __shfl_xor_sync(0xffffffffu, contrib, sh);
    }

    if (lane == 0) s_wsum[warp] = contrib;
    __syncthreads();
    if (threadIdx.x == 0) {
        int t = 0;
        #pragma unroll
        for (int w = 0; w < 8; w++) t += s_wsum[w];
        atomicAdd(&g_total, t);
        __threadfence();
        if (atomicAdd(&g_done, 1) == nblocks - 1) {
            const int tot = atomicAdd(&g_total, 0);
            out[0] = (float)((tot + ob[0]) >> 4);
        }
    }
}

extern "C" void kernel_launch(void* const* d_in, const int* in_sizes, int n_in,
                              void* d_out, int out_size) {
    const int B = in_sizes[0] / 640;
    const int sblocks = (B + 7) / 8;

    hx_phaseA<<<dim3(64, NQ), 256>>>(
        (const int*)d_in[2], (const int*)d_in[0], (const int*)d_in[1],
        (const int*)d_in[4], (const int*)d_in[6], B);
    hx_phaseB<<<sblocks, 256>>>(
        (const int*)d_in[2],
        (const int*)d_in[1],
        (const int*)d_in[3],
        (const int*)d_in[5],
        (const int*)d_in[7],
        (const int*)d_in[8],
        (const int*)d_in[9],
        (float*)d_out,
        B, sblocks);
}